// round 2
// baseline (speedup 1.0000x reference)
#include <cuda_runtime.h>
#include <cuda_fp16.h>
#include <mma.h>

using namespace nvcuda;

// Problem constants
#define DIMC   512
#define N3C    1536
#define MROWS  100352   // 8*256*49
#define WTOK   49
#define NWIN   2048     // 8*256 windows
#define ATT_SCALE 0.17677669529663687f  // 32^-0.5

// ---------------- scratch (static __device__ — no allocations allowed) ----------------
__device__ __half g_xhi[(size_t)MROWS * DIMC];   // 103 MB
__device__ __half g_xlo[(size_t)MROWS * DIMC];   // 103 MB
__device__ __half g_whi[(size_t)DIMC * N3C];     // 1.5 MB
__device__ __half g_wlo[(size_t)DIMC * N3C];     // 1.5 MB
__device__ float  g_qkv[(size_t)MROWS * N3C];    // 616 MB fp32 qkv (bias+scale fused)

// ---------------- fp32 -> split fp16 (hi + lo) converters ----------------
__global__ void conv_x_kernel(const float* __restrict__ in, int n4) {
    int i = blockIdx.x * blockDim.x + threadIdx.x;
    if (i < n4) {
        float4 v = reinterpret_cast<const float4*>(in)[i];
        __half h0 = __float2half_rn(v.x), h1 = __float2half_rn(v.y);
        __half h2 = __float2half_rn(v.z), h3 = __float2half_rn(v.w);
        __half l0 = __float2half_rn(v.x - __half2float(h0));
        __half l1 = __float2half_rn(v.y - __half2float(h1));
        __half l2 = __float2half_rn(v.z - __half2float(h2));
        __half l3 = __float2half_rn(v.w - __half2float(h3));
        reinterpret_cast<__half2*>(g_xhi)[2 * i]     = __halves2half2(h0, h1);
        reinterpret_cast<__half2*>(g_xhi)[2 * i + 1] = __halves2half2(h2, h3);
        reinterpret_cast<__half2*>(g_xlo)[2 * i]     = __halves2half2(l0, l1);
        reinterpret_cast<__half2*>(g_xlo)[2 * i + 1] = __halves2half2(l2, l3);
    }
}

__global__ void conv_w_kernel(const float* __restrict__ in, int n4) {
    int i = blockIdx.x * blockDim.x + threadIdx.x;
    if (i < n4) {
        float4 v = reinterpret_cast<const float4*>(in)[i];
        __half h0 = __float2half_rn(v.x), h1 = __float2half_rn(v.y);
        __half h2 = __float2half_rn(v.z), h3 = __float2half_rn(v.w);
        __half l0 = __float2half_rn(v.x - __half2float(h0));
        __half l1 = __float2half_rn(v.y - __half2float(h1));
        __half l2 = __float2half_rn(v.z - __half2float(h2));
        __half l3 = __float2half_rn(v.w - __half2float(h3));
        reinterpret_cast<__half2*>(g_whi)[2 * i]     = __halves2half2(h0, h1);
        reinterpret_cast<__half2*>(g_whi)[2 * i + 1] = __halves2half2(h2, h3);
        reinterpret_cast<__half2*>(g_wlo)[2 * i]     = __halves2half2(l0, l1);
        reinterpret_cast<__half2*>(g_wlo)[2 * i + 1] = __halves2half2(l2, l3);
    }
}

// ---------------- QKV GEMM with split-fp16 for q,k columns ----------------
// [100352,512] x [512,1536] -> [100352,1536] fp32.
// Tile 128x128x32, 8 warps (4M x 2N). q,k blocks (bn<8): acc += Ahi*Bhi + Alo*Bhi + Ahi*Blo.
// v blocks (bn>=8): acc += Ahi*Bhi only.
#define BM 128
#define BN 128
#define BK 32
#define ASTR 48    // halves per A row (96B, 32B-aligned)
#define BSTR 144   // halves per B row

#define GEMM_SMEM_BYTES (2 * BM * ASTR * 2 + 2 * BK * BSTR * 2)  // 43008

__global__ void __launch_bounds__(256) qkv_gemm_kernel(const float* __restrict__ bias) {
    extern __shared__ __align__(16) unsigned char gsm[];
    __half* As_hi = reinterpret_cast<__half*>(gsm);
    __half* As_lo = As_hi + BM * ASTR;
    __half* Bs_hi = As_lo + BM * ASTR;
    __half* Bs_lo = Bs_hi + BK * BSTR;
    float*  stageb = reinterpret_cast<float*>(gsm);  // epilogue aliases A tiles (24KB >= 12.3KB)

    const int tid  = threadIdx.x;
    const int warp = tid >> 5;
    const int lane = tid & 31;
    const int bm = blockIdx.x;  // 784
    const int bn = blockIdx.y;  // 12
    const int wm = warp & 3;
    const int wn = warp >> 2;
    const bool doSplit = (bn < 8);   // q,k columns need split precision

    wmma::fragment<wmma::accumulator, 16, 16, 16, float> acc[2][4];
#pragma unroll
    for (int mi = 0; mi < 2; mi++)
#pragma unroll
        for (int ni = 0; ni < 4; ni++)
            wmma::fill_fragment(acc[mi][ni], 0.0f);

    const size_t abase = (size_t)bm * BM * DIMC;
    const int arow = tid >> 2, acol = (tid & 3) * 8;   // 64 rows x 32 cols per pass
    const int brow = tid >> 4, bcol = (tid & 15) * 8;  // 16 rows x 128 cols per pass

    for (int kt = 0; kt < DIMC; kt += BK) {
        const size_t a0 = abase + (size_t)arow * DIMC + kt + acol;
        const size_t a1 = a0 + (size_t)64 * DIMC;
        *reinterpret_cast<uint4*>(&As_hi[arow * ASTR + acol]) =
            *reinterpret_cast<const uint4*>(&g_xhi[a0]);
        *reinterpret_cast<uint4*>(&As_hi[(arow + 64) * ASTR + acol]) =
            *reinterpret_cast<const uint4*>(&g_xhi[a1]);
        const size_t b0 = (size_t)(kt + brow) * N3C + bn * BN + bcol;
        const size_t b1 = b0 + (size_t)16 * N3C;
        *reinterpret_cast<uint4*>(&Bs_hi[brow * BSTR + bcol]) =
            *reinterpret_cast<const uint4*>(&g_whi[b0]);
        *reinterpret_cast<uint4*>(&Bs_hi[(brow + 16) * BSTR + bcol]) =
            *reinterpret_cast<const uint4*>(&g_whi[b1]);
        if (doSplit) {
            *reinterpret_cast<uint4*>(&As_lo[arow * ASTR + acol]) =
                *reinterpret_cast<const uint4*>(&g_xlo[a0]);
            *reinterpret_cast<uint4*>(&As_lo[(arow + 64) * ASTR + acol]) =
                *reinterpret_cast<const uint4*>(&g_xlo[a1]);
            *reinterpret_cast<uint4*>(&Bs_lo[brow * BSTR + bcol]) =
                *reinterpret_cast<const uint4*>(&g_wlo[b0]);
            *reinterpret_cast<uint4*>(&Bs_lo[(brow + 16) * BSTR + bcol]) =
                *reinterpret_cast<const uint4*>(&g_wlo[b1]);
        }
        __syncthreads();

#pragma unroll
        for (int kk = 0; kk < 2; kk++) {
            wmma::fragment<wmma::matrix_a, 16, 16, 16, __half, wmma::row_major> af_hi[2], af_lo[2];
            wmma::fragment<wmma::matrix_b, 16, 16, 16, __half, wmma::row_major> bf[4];
#pragma unroll
            for (int mi = 0; mi < 2; mi++)
                wmma::load_matrix_sync(af_hi[mi], &As_hi[(wm * 32 + mi * 16) * ASTR + kk * 16], ASTR);
            if (doSplit) {
#pragma unroll
                for (int mi = 0; mi < 2; mi++)
                    wmma::load_matrix_sync(af_lo[mi], &As_lo[(wm * 32 + mi * 16) * ASTR + kk * 16], ASTR);
            }
#pragma unroll
            for (int ni = 0; ni < 4; ni++)
                wmma::load_matrix_sync(bf[ni], &Bs_hi[(kk * 16) * BSTR + wn * 64 + ni * 16], BSTR);
#pragma unroll
            for (int mi = 0; mi < 2; mi++)
#pragma unroll
                for (int ni = 0; ni < 4; ni++)
                    wmma::mma_sync(acc[mi][ni], af_hi[mi], bf[ni], acc[mi][ni]);
            if (doSplit) {
#pragma unroll
                for (int mi = 0; mi < 2; mi++)
#pragma unroll
                    for (int ni = 0; ni < 4; ni++)
                        wmma::mma_sync(acc[mi][ni], af_lo[mi], bf[ni], acc[mi][ni]);
                // reuse bf registers for B_lo
#pragma unroll
                for (int ni = 0; ni < 4; ni++)
                    wmma::load_matrix_sync(bf[ni], &Bs_lo[(kk * 16) * BSTR + wn * 64 + ni * 16], BSTR);
#pragma unroll
                for (int mi = 0; mi < 2; mi++)
#pragma unroll
                    for (int ni = 0; ni < 4; ni++)
                        wmma::mma_sync(acc[mi][ni], af_hi[mi], bf[ni], acc[mi][ni]);
            }
        }
        __syncthreads();
    }

    // Epilogue: per-warp 16x24 stage (aliases A-tile smem), bias add, q scale, fp32 store
    float* stage = stageb + warp * (16 * 24);
    const float scl = (bn < 4) ? ATT_SCALE : 1.0f;
#pragma unroll
    for (int mi = 0; mi < 2; mi++) {
#pragma unroll
        for (int ni = 0; ni < 4; ni++) {
            wmma::store_matrix_sync(stage, acc[mi][ni], 24, wmma::mem_row_major);
            __syncwarp();
            const int gm = bm * BM + wm * 32 + mi * 16;
            const int gn = bn * BN + wn * 64 + ni * 16;
#pragma unroll
            for (int e = lane; e < 256; e += 32) {
                int r = e >> 4, c = e & 15;
                float v = (stage[r * 24 + c] + bias[gn + c]) * scl;
                g_qkv[(size_t)(gm + r) * N3C + gn + c] = v;
            }
            __syncwarp();
        }
    }
}

// ---------------- Attention: one CTA per window (49 tokens), all fp32 ----------------
#define KQSTR 52
#define VSTR  516
#define QT_F  (512 * KQSTR)
#define S_OFF (2 * QT_F)
#define ATT_SMEM_BYTES ((2 * QT_F + WTOK * KQSTR) * 4)  // 223184

__global__ void __launch_bounds__(512) attn_kernel(float* __restrict__ out) {
    extern __shared__ float sm[];
    float* Qt = sm;            // q transposed [c][i] (pre-scaled)
    float* KV = sm + QT_F;     // k transposed [c][j], later v natural [j][c]
    float* S  = sm + S_OFF;    // [49][52]

    const int w = blockIdx.x;
    const size_t base = (size_t)w * WTOK;
    const int tid = threadIdx.x;

    for (int idx = tid; idx < WTOK * DIMC; idx += 512) {
        int i = idx >> 9, c = idx & 511;
        const float* row = g_qkv + (base + i) * N3C;
        Qt[c * KQSTR + i] = row[c];
        KV[c * KQSTR + i] = row[512 + c];
    }
    __syncthreads();

    // S = q @ k^T, 2i x 4j register tiles: 325 tasks
    for (int t = tid; t < 325; t += 512) {
        int ig = t % 25, jg = t / 25;
        int i0 = ig * 2, j0 = jg * 4;
        float a0[4] = {0.f, 0.f, 0.f, 0.f};
        float a1[4] = {0.f, 0.f, 0.f, 0.f};
        for (int c = 0; c < DIMC; c++) {
            const float* qr = &Qt[c * KQSTR];
            const float* kr = &KV[c * KQSTR];
            float q0 = qr[i0], q1 = qr[i0 + 1];
            float k0 = kr[j0], k1 = kr[j0 + 1], k2 = kr[j0 + 2], k3 = kr[j0 + 3];
            a0[0] += q0 * k0; a0[1] += q0 * k1; a0[2] += q0 * k2; a0[3] += q0 * k3;
            a1[0] += q1 * k0; a1[1] += q1 * k1; a1[2] += q1 * k2; a1[3] += q1 * k3;
        }
#pragma unroll
        for (int jj = 0; jj < 4; jj++) {
            int j = j0 + jj;
            if (j < WTOK) {
                S[i0 * KQSTR + j] = a0[jj];
                if (i0 + 1 < WTOK) S[(i0 + 1) * KQSTR + j] = a1[jj];
            }
        }
    }
    __syncthreads();

    // Softmax per row
    if (tid < WTOK) {
        float* Sr = &S[tid * KQSTR];
        float m = -1e30f;
        for (int j = 0; j < WTOK; j++) m = fmaxf(m, Sr[j]);
        float s = 0.f;
        for (int j = 0; j < WTOK; j++) { float e = __expf(Sr[j] - m); Sr[j] = e; s += e; }
        float inv = 1.0f / s;
        for (int j = 0; j < WTOK; j++) Sr[j] *= inv;
    }
    __syncthreads();

    // Overwrite K smem with V in natural [j][c] layout
    for (int idx = tid; idx < WTOK * (DIMC / 4); idx += 512) {
        int i = idx >> 7, c4 = idx & 127;
        float4 v = *reinterpret_cast<const float4*>(&g_qkv[(base + i) * N3C + 1024 + c4 * 4]);
        *reinterpret_cast<float4*>(&KV[i * VSTR + c4 * 4]) = v;
    }
    __syncthreads();

    // out = S @ V
    for (int t = tid; t < 3200; t += 512) {
        int cc = t & 127, ig = t >> 7;
        int i0 = ig * 2, c = cc * 4;
        int i1 = (i0 + 1 < WTOK) ? (i0 + 1) : i0;
        const float* Sr0 = &S[i0 * KQSTR];
        const float* Sr1 = &S[i1 * KQSTR];
        float a0[4] = {0.f, 0.f, 0.f, 0.f};
        float a1[4] = {0.f, 0.f, 0.f, 0.f};
#pragma unroll 7
        for (int j = 0; j < WTOK; j++) {
            float4 v = *reinterpret_cast<const float4*>(&KV[j * VSTR + c]);
            float s0 = Sr0[j], s1 = Sr1[j];
            a0[0] += s0 * v.x; a0[1] += s0 * v.y; a0[2] += s0 * v.z; a0[3] += s0 * v.w;
            a1[0] += s1 * v.x; a1[1] += s1 * v.y; a1[2] += s1 * v.z; a1[3] += s1 * v.w;
        }
        *reinterpret_cast<float4*>(&out[(base + i0) * DIMC + c]) =
            make_float4(a0[0], a0[1], a0[2], a0[3]);
        if (i0 + 1 < WTOK) {
            *reinterpret_cast<float4*>(&out[(base + i0 + 1) * DIMC + c]) =
                make_float4(a1[0], a1[1], a1[2], a1[3]);
        }
    }
}

// ---------------- launch ----------------
extern "C" void kernel_launch(void* const* d_in, const int* in_sizes, int n_in,
                              void* d_out, int out_size) {
    const float* x    = (const float*)d_in[0];
    // d_in[1] (x_all) is unused by the reference computation.
    const float* W    = (const float*)d_in[2];
    const float* bqkv = (const float*)d_in[3];
    float* out = (float*)d_out;
    (void)in_sizes; (void)n_in; (void)out_size;

    {
        int n4 = (MROWS * DIMC) / 4;  // 12,845,056
        conv_x_kernel<<<(n4 + 255) / 256, 256>>>(x, n4);
    }
    {
        int n4 = (DIMC * N3C) / 4;    // 196,608
        conv_w_kernel<<<(n4 + 255) / 256, 256>>>(W, n4);
    }
    {
        dim3 grid(MROWS / BM, N3C / BN);  // 784 x 12
        qkv_gemm_kernel<<<grid, 256, GEMM_SMEM_BYTES>>>(bqkv);
    }
    {
        cudaFuncSetAttribute(attn_kernel,
                             cudaFuncAttributeMaxDynamicSharedMemorySize,
                             ATT_SMEM_BYTES);
        attn_kernel<<<NWIN, 512, ATT_SMEM_BYTES>>>(out);
    }
}